// round 1
// baseline (speedup 1.0000x reference)
#include <cuda_runtime.h>
#include <math.h>

#define BQ 128
#define SS 30
#define HH 768
#define II 3072
#define LL 12
#define NHD 12
#define HD 64
#define EE 15
#define DD 14
#define RR 29
#define LRK 8
#define TN (BQ*SS)        // 3840 tokens
#define ELR (EE*LRK)      // 120
#define SCALF 2.0f

// ---------------- scratch (device globals; no allocation) ----------------
__device__ float g_h[TN*HH];
__device__ float g_nx[TN*HH];
__device__ float g_q[TN*HH];
__device__ float g_k[TN*HH];
__device__ float g_v[TN*HH];
__device__ float g_ctx[TN*HH];
__device__ float g_att[TN*HH];
__device__ float g_res1[TN*HH];
__device__ float g_nres[TN*HH];
__device__ float g_hid[TN*II];
__device__ float g_bout[TN*HH];
__device__ float g_u[TN*ELR];
__device__ float g_vv[TN*ELR];
__device__ float g_t[TN*ELR];
__device__ float g_M[EE*LRK*LRK];
__device__ float g_gate[BQ*DD];

__device__ __forceinline__ float gelu_f(float x) {
    return 0.5f * x * (1.0f + erff(x * 0.70710678118654752f));
}

// ---------------- embed: h = concat(cls, region_features) ----------------
__global__ void embed_kernel(const float* __restrict__ rf, const float* __restrict__ cls) {
    int idx = blockIdx.x * 256 + threadIdx.x;
    if (idx >= TN * HH) return;
    int t = idx / HH, j = idx - t * HH;
    int s = t % SS, b = t / SS;
    g_h[idx] = (s == 0) ? cls[j] : rf[(b * RR + (s - 1)) * HH + j];
}

// ---------------- LayerNorm over H=768, one block per token ----------------
__global__ void ln_kernel(const float* __restrict__ in, float* __restrict__ out,
                          const float* __restrict__ g, const float* __restrict__ b,
                          float eps) {
    int t = blockIdx.x;
    int tid = threadIdx.x;
    const float* x = in + t * HH;
    __shared__ float s1[256], s2[256];
    float xv[3];
    float a = 0.f, sq = 0.f;
#pragma unroll
    for (int i = 0; i < 3; i++) {
        float v = x[tid + i * 256];
        xv[i] = v; a += v; sq += v * v;
    }
    s1[tid] = a; s2[tid] = sq;
    __syncthreads();
    for (int o = 128; o > 0; o >>= 1) {
        if (tid < o) { s1[tid] += s1[tid + o]; s2[tid] += s2[tid + o]; }
        __syncthreads();
    }
    float mean = s1[0] * (1.0f / 768.0f);
    float var = s2[0] * (1.0f / 768.0f) - mean * mean;
    float r = rsqrtf(var + eps);
#pragma unroll
    for (int i = 0; i < 3; i++) {
        int j = tid + i * 256;
        out[t * HH + j] = (xv[i] - mean) * r * g[j] + b[j];
    }
}

// ---------------- elementwise add ----------------
__global__ void add_kernel(const float* __restrict__ a, const float* __restrict__ b,
                           float* __restrict__ c, int n) {
    int i = blockIdx.x * 256 + threadIdx.x;
    if (i < n) c[i] = a[i] + b[i];
}

// ---------------- SGEMM: C[3840,N] = A[3840,K] @ W[N,K]^T (+bias)(gelu)(+add) ----------------
// 64x64 tile, BK=16, 256 threads, 4x4 microtile.
__global__ void gemm_kernel(const float* __restrict__ A, const float* __restrict__ W,
                            const float* __restrict__ bias, const float* __restrict__ add,
                            float* __restrict__ C, int N, int K, int act) {
    __shared__ float As[16][64];
    __shared__ float Bs[16][64];
    int bm = blockIdx.y * 64, bn = blockIdx.x * 64;
    int tid = threadIdx.x;
    int tx = tid & 15, ty = tid >> 4;
    int lr = tid >> 2;                 // 0..63
    int lc = (tid & 3) << 2;           // 0,4,8,12
    float acc[4][4] = {};
    const float* Aptr = A + (bm + lr) * K + lc;
    int wrow = bn + lr;
    const float* Wptr = W + (size_t)wrow * K + lc;
    for (int k0 = 0; k0 < K; k0 += 16) {
        float4 a4 = *(const float4*)(Aptr + k0);
        float4 b4 = (wrow < N) ? *(const float4*)(Wptr + k0) : make_float4(0.f, 0.f, 0.f, 0.f);
        As[lc + 0][lr] = a4.x; As[lc + 1][lr] = a4.y; As[lc + 2][lr] = a4.z; As[lc + 3][lr] = a4.w;
        Bs[lc + 0][lr] = b4.x; Bs[lc + 1][lr] = b4.y; Bs[lc + 2][lr] = b4.z; Bs[lc + 3][lr] = b4.w;
        __syncthreads();
#pragma unroll
        for (int kk = 0; kk < 16; kk++) {
            float4 ra = *(const float4*)&As[kk][ty << 2];
            float4 rb = *(const float4*)&Bs[kk][tx << 2];
            float raa[4] = {ra.x, ra.y, ra.z, ra.w};
            float rbb[4] = {rb.x, rb.y, rb.z, rb.w};
#pragma unroll
            for (int i = 0; i < 4; i++)
#pragma unroll
                for (int j = 0; j < 4; j++)
                    acc[i][j] += raa[i] * rbb[j];
        }
        __syncthreads();
    }
#pragma unroll
    for (int i = 0; i < 4; i++) {
        int m = bm + (ty << 2) + i;
#pragma unroll
        for (int j = 0; j < 4; j++) {
            int n = bn + (tx << 2) + j;
            if (n < N) {
                float v = acc[i][j];
                if (bias) v += bias[n];
                if (act) v = gelu_f(v);
                if (add) v += add[(size_t)m * N + n];
                C[(size_t)m * N + n] = v;
            }
        }
    }
}

// ---------------- attention: one block per (batch, head) ----------------
__global__ void attn_kernel() {
    int bh = blockIdx.x;
    int b = bh / NHD, hh = bh - b * NHD;
    __shared__ float sq[SS][HD], sk[SS][HD], sv[SS][HD], sc[SS][SS + 1];
    int tid = threadIdx.x;
    int base = b * SS;
    for (int i = tid; i < SS * HD; i += 256) {
        int s = i >> 6, d = i & 63;
        int gi = (base + s) * HH + hh * HD + d;
        sq[s][d] = g_q[gi]; sk[s][d] = g_k[gi]; sv[s][d] = g_v[gi];
    }
    __syncthreads();
    for (int i = tid; i < SS * SS; i += 256) {
        int r = i / SS, c = i - r * SS;
        float s = 0.f;
#pragma unroll
        for (int d = 0; d < HD; d++) s += sq[r][d] * sk[c][d];
        sc[r][c] = s * 0.125f;
    }
    __syncthreads();
    if (tid < SS) {
        float mx = -1e30f;
        for (int c = 0; c < SS; c++) mx = fmaxf(mx, sc[tid][c]);
        float sm = 0.f;
        for (int c = 0; c < SS; c++) { float e = expf(sc[tid][c] - mx); sc[tid][c] = e; sm += e; }
        float inv = 1.0f / sm;
        for (int c = 0; c < SS; c++) sc[tid][c] *= inv;
    }
    __syncthreads();
    for (int i = tid; i < SS * HD; i += 256) {
        int s = i >> 6, d = i & 63;
        float o = 0.f;
#pragma unroll
        for (int c = 0; c < SS; c++) o += sc[s][c] * sv[c][d];
        g_ctx[(base + s) * HH + hh * HD + d] = o;
    }
}

// ---------------- per-disease classifiers -> gate[b,d] ----------------
__global__ void cls_kernel(const float* __restrict__ mask,
                           const float* __restrict__ cw1, const float* __restrict__ cb1,
                           const float* __restrict__ clg, const float* __restrict__ clb,
                           const float* __restrict__ cw2, const float* __restrict__ cb2) {
    int b = blockIdx.x, d = blockIdx.y;
    int tid = threadIdx.x;
    __shared__ float pooled[HH];
    __shared__ float h1[384];
    __shared__ float r1[256], r2[256];
    float cnt = 0.f;
    for (int r = 0; r < RR; r++) cnt += (mask[r * DD + d] > 0.f) ? 1.f : 0.f;
    float inv = 1.0f / fmaxf(cnt, 1.0f);
    for (int j = tid; j < HH; j += 256) {
        float s = 0.f;
        for (int r = 0; r < RR; r++)
            if (mask[r * DD + d] > 0.f) s += g_att[(b * SS + 1 + r) * HH + j];
        pooled[j] = s * inv;
    }
    __syncthreads();
    for (int k = tid; k < 384; k += 256) {
        const float* wrow = cw1 + ((size_t)d * 384 + k) * HH;
        float s = 0.f;
        for (int j = 0; j < HH; j++) s += pooled[j] * wrow[j];
        h1[k] = s + cb1[d * 384 + k];
    }
    __syncthreads();
    float a = 0.f, sq = 0.f;
    for (int k = tid; k < 384; k += 256) { float v = h1[k]; a += v; sq += v * v; }
    r1[tid] = a; r2[tid] = sq;
    __syncthreads();
    for (int o = 128; o > 0; o >>= 1) {
        if (tid < o) { r1[tid] += r1[tid + o]; r2[tid] += r2[tid + o]; }
        __syncthreads();
    }
    float mean = r1[0] * (1.0f / 384.0f);
    float var = r2[0] * (1.0f / 384.0f) - mean * mean;
    float rn = rsqrtf(var + 1e-5f);
    __syncthreads();
    float p = 0.f;
    for (int k = tid; k < 384; k += 256) {
        float v = (h1[k] - mean) * rn * clg[d * 384 + k] + clb[d * 384 + k];
        v = gelu_f(v);
        p += v * cw2[d * 384 + k];
    }
    r1[tid] = p;
    __syncthreads();
    for (int o = 128; o > 0; o >>= 1) {
        if (tid < o) r1[tid] += r1[tid + o];
        __syncthreads();
    }
    if (tid == 0) {
        float pred = r1[0] + cb2[d];
        g_gate[b * DD + d] = (cnt > 0.f && pred > 0.f) ? 1.f : 0.f;
    }
}

// ---------------- M[e] = Bu_e^T @ Ad_e^T  (8x8 per expert) ----------------
__global__ void m_kernel(const float* __restrict__ bu, const float* __restrict__ ad) {
    int e = blockIdx.x;
    int r = threadIdx.x >> 3, c = threadIdx.x & 7;
    const float* bup = bu + (size_t)e * II * LRK;          // [3072,8]
    const float* adp = ad + ((size_t)e * LRK + c) * II;    // row c of Ad_e [8,3072]
    float s = 0.f;
    for (int i = 0; i < II; i++) s += bup[i * LRK + r] * adp[i];
    g_M[(e * LRK + r) * LRK + c] = s;
}

// ---------------- t = v + SCAL * u @ M ----------------
__global__ void t_kernel() {
    int token = blockIdx.x;
    int er = threadIdx.x;                  // 0..119
    int e = er >> 3, r = er & 7;
    __shared__ float su[ELR];
    su[er] = g_u[token * ELR + er];
    __syncthreads();
    float s = 0.f;
#pragma unroll
    for (int q = 0; q < LRK; q++) s += su[e * LRK + q] * g_M[(e * LRK + q) * LRK + r];
    g_t[token * ELR + er] = g_vv[token * ELR + er] + SCALF * s;
}

// ---------------- expert mix: per-token LN over each active expert output ----------------
__global__ void comb_kernel(const float* __restrict__ bd, const float* __restrict__ mask) {
    int token = blockIdx.x;
    int b = token / SS, s = token - b * SS;
    int tid = threadIdx.x;
    __shared__ float r1[256], r2[256];
    __shared__ float sw[16];
    if (tid < EE) {
        float a;
        if (tid == 14) a = 1.f;
        else a = (s > 0 && mask[(s - 1) * DD + tid] > 0.f) ? g_gate[b * DD + tid] : 0.f;
        sw[tid] = a;
    }
    __syncthreads();
    float nact = 0.f;
#pragma unroll
    for (int e = 0; e < EE; e++) nact += sw[e];
    float wt = 1.0f / fmaxf(nact, 1.0f);
    float bo0[3], acc[3] = {0.f, 0.f, 0.f};
#pragma unroll
    for (int i = 0; i < 3; i++) bo0[i] = g_bout[token * HH + tid + i * 256];
    for (int e = 0; e < EE; e++) {
        if (sw[e] == 0.f) continue;
        float t8[8];
        const float* tp = g_t + token * ELR + e * LRK;
#pragma unroll
        for (int r = 0; r < 8; r++) t8[r] = tp[r];
        float o[3];
        float a = 0.f, sq = 0.f;
#pragma unroll
        for (int i = 0; i < 3; i++) {
            int j = tid + i * 256;
            const float* bdp = bd + ((size_t)e * HH + j) * LRK;
            float dv = 0.f;
#pragma unroll
            for (int r = 0; r < 8; r++) dv += t8[r] * bdp[r];
            float ov = bo0[i] + SCALF * dv;
            o[i] = ov; a += ov; sq += ov * ov;
        }
        r1[tid] = a; r2[tid] = sq;
        __syncthreads();
        for (int off = 128; off > 0; off >>= 1) {
            if (tid < off) { r1[tid] += r1[tid + off]; r2[tid] += r2[tid + off]; }
            __syncthreads();
        }
        float mean = r1[0] * (1.0f / 768.0f);
        float var = r2[0] * (1.0f / 768.0f) - mean * mean;
        float rn = rsqrtf(var + 1e-5f);
#pragma unroll
        for (int i = 0; i < 3; i++) acc[i] += wt * (o[i] - mean) * rn;
        __syncthreads();
    }
#pragma unroll
    for (int i = 0; i < 3; i++) {
        int j = tid + i * 256;
        g_h[token * HH + j] = acc[i] + g_res1[token * HH + j];
    }
}

// ---------------- host launcher ----------------
extern "C" void kernel_launch(void* const* d_in, const int* in_sizes, int n_in,
                              void* d_out, int out_size) {
    const float* rf   = (const float*)d_in[0];
    const float* cls  = (const float*)d_in[1];
    const float* ln1g = (const float*)d_in[2];
    const float* ln1b = (const float*)d_in[3];
    const float* ln2g = (const float*)d_in[4];
    const float* ln2b = (const float*)d_in[5];
    const float* wq   = (const float*)d_in[6];
    const float* bq   = (const float*)d_in[7];
    const float* wk   = (const float*)d_in[8];
    const float* bk   = (const float*)d_in[9];
    const float* wv   = (const float*)d_in[10];
    const float* bv   = (const float*)d_in[11];
    const float* wo   = (const float*)d_in[12];
    const float* bo   = (const float*)d_in[13];
    const float* wi   = (const float*)d_in[14];
    const float* bi   = (const float*)d_in[15];
    const float* wof  = (const float*)d_in[16];
    const float* bof  = (const float*)d_in[17];
    const float* lnfg = (const float*)d_in[18];
    const float* lnfb = (const float*)d_in[19];
    const float* au   = (const float*)d_in[20];
    const float* bu   = (const float*)d_in[21];
    const float* ad   = (const float*)d_in[22];
    const float* bd   = (const float*)d_in[23];
    const float* cw1  = (const float*)d_in[24];
    const float* cb1  = (const float*)d_in[25];
    const float* clg  = (const float*)d_in[26];
    const float* clb  = (const float*)d_in[27];
    const float* cw2  = (const float*)d_in[28];
    const float* cb2  = (const float*)d_in[29];
    const float* maskp= (const float*)d_in[30];
    float* out = (float*)d_out;

    float *h, *nx, *q, *k, *v, *ctx, *att, *res1, *nres, *hid, *bout, *u, *vv;
    cudaGetSymbolAddress((void**)&h,    g_h);
    cudaGetSymbolAddress((void**)&nx,   g_nx);
    cudaGetSymbolAddress((void**)&q,    g_q);
    cudaGetSymbolAddress((void**)&k,    g_k);
    cudaGetSymbolAddress((void**)&v,    g_v);
    cudaGetSymbolAddress((void**)&ctx,  g_ctx);
    cudaGetSymbolAddress((void**)&att,  g_att);
    cudaGetSymbolAddress((void**)&res1, g_res1);
    cudaGetSymbolAddress((void**)&nres, g_nres);
    cudaGetSymbolAddress((void**)&hid,  g_hid);
    cudaGetSymbolAddress((void**)&bout, g_bout);
    cudaGetSymbolAddress((void**)&u,    g_u);
    cudaGetSymbolAddress((void**)&vv,   g_vv);

    dim3 g768(HH / 64, TN / 64);
    dim3 g3072(II / 64, TN / 64);
    dim3 g120((ELR + 63) / 64, TN / 64);
    int nel = TN * HH;
    int nblk = (nel + 255) / 256;

    embed_kernel<<<nblk, 256>>>(rf, cls);

    for (int i = 0; i < LL; i++) {
        ln_kernel<<<TN, 256>>>(h, nx, ln1g + i * HH, ln1b + i * HH, 1e-12f);
        gemm_kernel<<<g768, 256>>>(nx, wq + (size_t)i * HH * HH, bq + i * HH, nullptr, q, HH, HH, 0);
        gemm_kernel<<<g768, 256>>>(nx, wk + (size_t)i * HH * HH, bk + i * HH, nullptr, k, HH, HH, 0);
        gemm_kernel<<<g768, 256>>>(nx, wv + (size_t)i * HH * HH, bv + i * HH, nullptr, v, HH, HH, 0);
        attn_kernel<<<BQ * NHD, 256>>>();
        gemm_kernel<<<g768, 256>>>(ctx, wo + (size_t)i * HH * HH, bo + i * HH, nullptr, att, HH, HH, 0);
        add_kernel<<<nblk, 256>>>(att, h, res1, nel);
        ln_kernel<<<TN, 256>>>(res1, nres, ln2g + i * HH, ln2b + i * HH, 1e-12f);
        gemm_kernel<<<g3072, 256>>>(nres, wi + (size_t)i * II * HH, bi + i * II, nullptr, hid, II, HH, 1);
        if (i & 1) {
            gemm_kernel<<<g768, 256>>>(hid, wof + (size_t)i * HH * II, bof + i * HH, res1, h, HH, II, 0);
        } else {
            int ei = i / 2;
            gemm_kernel<<<g768, 256>>>(hid, wof + (size_t)i * HH * II, bof + i * HH, nullptr, bout, HH, II, 0);
            dim3 gc(BQ, DD);
            cls_kernel<<<gc, 256>>>(maskp,
                                    cw1 + (size_t)ei * DD * 384 * HH,
                                    cb1 + (size_t)ei * DD * 384,
                                    clg + (size_t)ei * DD * 384,
                                    clb + (size_t)ei * DD * 384,
                                    cw2 + (size_t)ei * DD * 384,
                                    cb2 + (size_t)ei * DD);
            m_kernel<<<EE, 64>>>(bu + (size_t)ei * EE * II * LRK,
                                 ad + (size_t)ei * EE * LRK * II);
            gemm_kernel<<<g120, 256>>>(nres, au + (size_t)ei * EE * LRK * HH, nullptr, nullptr, u, ELR, HH, 0);
            gemm_kernel<<<g120, 256>>>(hid, ad + (size_t)ei * EE * LRK * II, nullptr, nullptr, vv, ELR, II, 0);
            t_kernel<<<TN, ELR>>>();
            comb_kernel<<<TN, 256>>>(bd + (size_t)ei * EE * HH * LRK, maskp);
        }
    }
    ln_kernel<<<TN, 256>>>(h, out, lnfg, lnfb, 1e-12f);
}

// round 4
// speedup vs baseline: 1.0873x; 1.0873x over previous
#include <cuda_runtime.h>
#include <math.h>
#include <stdint.h>

#define BQ 128
#define SS 30
#define HH 768
#define II 3072
#define LL 12
#define NHD 12
#define HD 64
#define EE 15
#define DD 14
#define RR 29
#define LRK 8
#define TN (BQ*SS)        // 3840 tokens
#define ELR (EE*LRK)      // 120
#define SCALF 2.0f

// ---------------- scratch (device globals; no allocation) ----------------
__device__ float g_h[TN*HH];
__device__ float g_nx[TN*HH];
__device__ float g_q[TN*HH];
__device__ float g_k[TN*HH];
__device__ float g_v[TN*HH];
__device__ float g_ctx[TN*HH];
__device__ float g_att[TN*HH];
__device__ float g_res1[TN*HH];
__device__ float g_nres[TN*HH];
__device__ float g_hid[TN*II];
__device__ float g_bout[TN*HH];
__device__ float g_u[TN*ELR];
__device__ float g_vv[TN*ELR];
__device__ float g_t[TN*ELR];
__device__ float g_M[EE*LRK*LRK];
__device__ float g_gate[BQ*DD];

__device__ __forceinline__ float gelu_f(float x) {
    return 0.5f * x * (1.0f + erff(x * 0.70710678118654752f));
}

// ---------------- embed ----------------
__global__ void embed_kernel(const float* __restrict__ rf, const float* __restrict__ cls) {
    int idx = blockIdx.x * 256 + threadIdx.x;
    if (idx >= TN * HH) return;
    int t = idx / HH, j = idx - t * HH;
    int s = t % SS, b = t / SS;
    g_h[idx] = (s == 0) ? cls[j] : rf[(b * RR + (s - 1)) * HH + j];
}

// ---------------- LayerNorm (H=768), optional fused residual add ----------------
// res = a + (b ? b : 0); if res_out, write res; norm_out = LN(res)*g + bb
__global__ void ln_kernel(const float* __restrict__ a, const float* __restrict__ b,
                          float* __restrict__ res_out, float* __restrict__ norm_out,
                          const float* __restrict__ g, const float* __restrict__ bb,
                          float eps) {
    int t = blockIdx.x;
    int tid = threadIdx.x;
    const float* xa = a + (size_t)t * HH;
    const float* xb = b ? b + (size_t)t * HH : nullptr;
    __shared__ float s1[256], s2[256];
    float xv[3];
    float acc = 0.f, sq = 0.f;
#pragma unroll
    for (int i = 0; i < 3; i++) {
        int j = tid + i * 256;
        float v = xa[j];
        if (xb) v += xb[j];
        xv[i] = v; acc += v; sq += v * v;
        if (res_out) res_out[(size_t)t * HH + j] = v;
    }
    s1[tid] = acc; s2[tid] = sq;
    __syncthreads();
    for (int o = 128; o > 0; o >>= 1) {
        if (tid < o) { s1[tid] += s1[tid + o]; s2[tid] += s2[tid + o]; }
        __syncthreads();
    }
    float mean = s1[0] * (1.0f / 768.0f);
    float var = s2[0] * (1.0f / 768.0f) - mean * mean;
    float r = rsqrtf(var + eps);
#pragma unroll
    for (int i = 0; i < 3; i++) {
        int j = tid + i * 256;
        norm_out[(size_t)t * HH + j] = (xv[i] - mean) * r * g[j] + bb[j];
    }
}

// ---------------- packed-f32x2 GEMM ----------------
// C[M,N] = A[M,K] @ W[N,K]^T (+bias)(gelu)(+add)
// BM=128, BN=128, BK=16. 256 threads, 8 warps (2x4), thread tile 8x8.
// Accumulators packed in f32x2 pairs along N; fma.rn.f32x2 doubles fp32 rate.
#define SP 132
__global__ void __launch_bounds__(256, 2)
pgemm_kernel(const float* __restrict__ A, const float* __restrict__ W,
             const float* __restrict__ bias, const float* __restrict__ add,
             float* __restrict__ C, int N, int K, int act) {
    __shared__ float As[16][SP];
    __shared__ float Ws[16][SP];
    int bm = blockIdx.y * 128, bn = blockIdx.x * 128;
    int tid = threadIdx.x;
    int warp = tid >> 5, lane = tid & 31;
    int wm = warp >> 2, wn = warp & 3;           // 2 x 4 warps
    int lm = lane >> 2, ln = lane & 3;           // 8 x 4 lanes
    int r0 = wm * 64 + lm * 8;                   // 8 rows
    int c0 = wn * 32 + ln * 8;                   // 8 cols

    int lrow = tid >> 2;                         // 0..63
    int lcol = (tid & 3) << 2;                   // 0,4,8,12
    const float* Ap0 = A + (size_t)(bm + lrow) * K + lcol;
    const float* Ap1 = A + (size_t)(bm + lrow + 64) * K + lcol;
    const float* Wp0 = W + (size_t)(bn + lrow) * K + lcol;
    const float* Wp1 = W + (size_t)(bn + lrow + 64) * K + lcol;

    unsigned long long acc[8][4];
#pragma unroll
    for (int i = 0; i < 8; i++)
#pragma unroll
        for (int j = 0; j < 4; j++) acc[i][j] = 0ull;

    float4 ra0 = *(const float4*)(Ap0);
    float4 ra1 = *(const float4*)(Ap1);
    float4 rw0 = *(const float4*)(Wp0);
    float4 rw1 = *(const float4*)(Wp1);

    for (int k0 = 0; k0 < K; k0 += 16) {
        {
            As[lcol + 0][lrow] = ra0.x; As[lcol + 1][lrow] = ra0.y;
            As[lcol + 2][lrow] = ra0.z; As[lcol + 3][lrow] = ra0.w;
            As[lcol + 0][lrow + 64] = ra1.x; As[lcol + 1][lrow + 64] = ra1.y;
            As[lcol + 2][lrow + 64] = ra1.z; As[lcol + 3][lrow + 64] = ra1.w;
            Ws[lcol + 0][lrow] = rw0.x; Ws[lcol + 1][lrow] = rw0.y;
            Ws[lcol + 2][lrow] = rw0.z; Ws[lcol + 3][lrow] = rw0.w;
            Ws[lcol + 0][lrow + 64] = rw1.x; Ws[lcol + 1][lrow + 64] = rw1.y;
            Ws[lcol + 2][lrow + 64] = rw1.z; Ws[lcol + 3][lrow + 64] = rw1.w;
        }
        __syncthreads();
        if (k0 + 16 < K) {
            ra0 = *(const float4*)(Ap0 + k0 + 16);
            ra1 = *(const float4*)(Ap1 + k0 + 16);
            rw0 = *(const float4*)(Wp0 + k0 + 16);
            rw1 = *(const float4*)(Wp1 + k0 + 16);
        }
#pragma unroll
        for (int k = 0; k < 16; k++) {
            float4 a0 = *(const float4*)&As[k][r0];
            float4 a1 = *(const float4*)&As[k][r0 + 4];
            ulonglong2 b0 = *(const ulonglong2*)&Ws[k][c0];
            ulonglong2 b1 = *(const ulonglong2*)&Ws[k][c0 + 4];
            unsigned long long bp[4] = {b0.x, b0.y, b1.x, b1.y};
            float av[8] = {a0.x, a0.y, a0.z, a0.w, a1.x, a1.y, a1.z, a1.w};
            unsigned long long ap[8];
#pragma unroll
            for (int i = 0; i < 8; i++)
                asm("mov.b64 %0, {%1, %1};" : "=l"(ap[i]) : "f"(av[i]));
#pragma unroll
            for (int i = 0; i < 8; i++)
#pragma unroll
                for (int j = 0; j < 4; j++)
                    asm("fma.rn.f32x2 %0, %1, %2, %0;"
                        : "+l"(acc[i][j]) : "l"(ap[i]), "l"(bp[j]));
        }
        __syncthreads();
    }

    // epilogue
    float bsv[8];
    if (bias) {
#pragma unroll
        for (int j = 0; j < 8; j++) bsv[j] = bias[bn + c0 + j];
    }
#pragma unroll
    for (int i = 0; i < 8; i++) {
        int row = bm + r0 + i;
        float o[8];
#pragma unroll
        for (int j = 0; j < 4; j++) {
            float lo, hi;
            asm("mov.b64 {%0, %1}, %2;" : "=f"(lo), "=f"(hi) : "l"(acc[i][j]));
            o[2 * j] = lo; o[2 * j + 1] = hi;
        }
        if (bias) {
#pragma unroll
            for (int j = 0; j < 8; j++) o[j] += bsv[j];
        }
        if (act) {
#pragma unroll
            for (int j = 0; j < 8; j++) o[j] = gelu_f(o[j]);
        }
        float* cp = &C[(size_t)row * N + bn + c0];
        if (add) {
            const float* ap2 = &add[(size_t)row * N + bn + c0];
            float4 d0 = *(const float4*)(ap2);
            float4 d1 = *(const float4*)(ap2 + 4);
            o[0] += d0.x; o[1] += d0.y; o[2] += d0.z; o[3] += d0.w;
            o[4] += d1.x; o[5] += d1.y; o[6] += d1.z; o[7] += d1.w;
        }
        *(float4*)(cp) = make_float4(o[0], o[1], o[2], o[3]);
        *(float4*)(cp + 4) = make_float4(o[4], o[5], o[6], o[7]);
    }
}

// ---------------- fp32 SGEMM (skinny LoRA GEMMs, N=120) ----------------
__global__ void gemm_kernel(const float* __restrict__ A, const float* __restrict__ W,
                            const float* __restrict__ bias, const float* __restrict__ add,
                            float* __restrict__ C, int N, int K, int act) {
    __shared__ float As[16][64];
    __shared__ float Bs[16][64];
    int bm = blockIdx.y * 64, bn = blockIdx.x * 64;
    int tid = threadIdx.x;
    int tx = tid & 15, ty = tid >> 4;
    int lr = tid >> 2;
    int lc = (tid & 3) << 2;
    float acc[4][4] = {};
    const float* Aptr = A + (bm + lr) * K + lc;
    int wrow = bn + lr;
    const float* Wptr = W + (size_t)wrow * K + lc;
    for (int k0 = 0; k0 < K; k0 += 16) {
        float4 a4 = *(const float4*)(Aptr + k0);
        float4 b4 = (wrow < N) ? *(const float4*)(Wptr + k0) : make_float4(0.f, 0.f, 0.f, 0.f);
        As[lc + 0][lr] = a4.x; As[lc + 1][lr] = a4.y; As[lc + 2][lr] = a4.z; As[lc + 3][lr] = a4.w;
        Bs[lc + 0][lr] = b4.x; Bs[lc + 1][lr] = b4.y; Bs[lc + 2][lr] = b4.z; Bs[lc + 3][lr] = b4.w;
        __syncthreads();
#pragma unroll
        for (int kk = 0; kk < 16; kk++) {
            float4 ra = *(const float4*)&As[kk][ty << 2];
            float4 rb = *(const float4*)&Bs[kk][tx << 2];
            float raa[4] = {ra.x, ra.y, ra.z, ra.w};
            float rbb[4] = {rb.x, rb.y, rb.z, rb.w};
#pragma unroll
            for (int i = 0; i < 4; i++)
#pragma unroll
                for (int j = 0; j < 4; j++)
                    acc[i][j] += raa[i] * rbb[j];
        }
        __syncthreads();
    }
#pragma unroll
    for (int i = 0; i < 4; i++) {
        int m = bm + (ty << 2) + i;
#pragma unroll
        for (int j = 0; j < 4; j++) {
            int n = bn + (tx << 2) + j;
            if (n < N) {
                float v = acc[i][j];
                if (bias) v += bias[n];
                if (act) v = gelu_f(v);
                if (add) v += add[(size_t)m * N + n];
                C[(size_t)m * N + n] = v;
            }
        }
    }
}

// ---------------- attention: one block per (batch, head) ----------------
__global__ void attn_kernel() {
    int bh = blockIdx.x;
    int b = bh / NHD, hh = bh - b * NHD;
    __shared__ float sq[SS][HD], sk[SS][HD], sv[SS][HD], sc[SS][SS + 1];
    int tid = threadIdx.x;
    int base = b * SS;
    for (int i = tid; i < SS * HD; i += 256) {
        int s = i >> 6, d = i & 63;
        int gi = (base + s) * HH + hh * HD + d;
        sq[s][d] = g_q[gi]; sk[s][d] = g_k[gi]; sv[s][d] = g_v[gi];
    }
    __syncthreads();
    for (int i = tid; i < SS * SS; i += 256) {
        int r = i / SS, c = i - r * SS;
        float s = 0.f;
#pragma unroll
        for (int d = 0; d < HD; d++) s += sq[r][d] * sk[c][d];
        sc[r][c] = s * 0.125f;
    }
    __syncthreads();
    if (tid < SS) {
        float mx = -1e30f;
        for (int c = 0; c < SS; c++) mx = fmaxf(mx, sc[tid][c]);
        float sm = 0.f;
        for (int c = 0; c < SS; c++) { float e = expf(sc[tid][c] - mx); sc[tid][c] = e; sm += e; }
        float inv = 1.0f / sm;
        for (int c = 0; c < SS; c++) sc[tid][c] *= inv;
    }
    __syncthreads();
    for (int i = tid; i < SS * HD; i += 256) {
        int s = i >> 6, d = i & 63;
        float o = 0.f;
#pragma unroll
        for (int c = 0; c < SS; c++) o += sc[s][c] * sv[c][d];
        g_ctx[(base + s) * HH + hh * HD + d] = o;
    }
}

// ---------------- per-disease classifiers -> gate[b,d] ----------------
__global__ void cls_kernel(const float* __restrict__ mask,
                           const float* __restrict__ cw1, const float* __restrict__ cb1,
                           const float* __restrict__ clg, const float* __restrict__ clb,
                           const float* __restrict__ cw2, const float* __restrict__ cb2) {
    int b = blockIdx.x, d = blockIdx.y;
    int tid = threadIdx.x;
    __shared__ float pooled[HH];
    __shared__ float h1[384];
    __shared__ float r1[256], r2[256];
    float cnt = 0.f;
    for (int r = 0; r < RR; r++) cnt += (mask[r * DD + d] > 0.f) ? 1.f : 0.f;
    float inv = 1.0f / fmaxf(cnt, 1.0f);
    for (int j = tid; j < HH; j += 256) {
        float s = 0.f;
        for (int r = 0; r < RR; r++)
            if (mask[r * DD + d] > 0.f) s += g_att[(b * SS + 1 + r) * HH + j];
        pooled[j] = s * inv;
    }
    __syncthreads();
    for (int k = tid; k < 384; k += 256) {
        const float* wrow = cw1 + ((size_t)d * 384 + k) * HH;
        float s = 0.f;
        for (int j = 0; j < HH; j++) s += pooled[j] * wrow[j];
        h1[k] = s + cb1[d * 384 + k];
    }
    __syncthreads();
    float a = 0.f, sq = 0.f;
    for (int k = tid; k < 384; k += 256) { float v = h1[k]; a += v; sq += v * v; }
    r1[tid] = a; r2[tid] = sq;
    __syncthreads();
    for (int o = 128; o > 0; o >>= 1) {
        if (tid < o) { r1[tid] += r1[tid + o]; r2[tid] += r2[tid + o]; }
        __syncthreads();
    }
    float mean = r1[0] * (1.0f / 384.0f);
    float var = r2[0] * (1.0f / 384.0f) - mean * mean;
    float rn = rsqrtf(var + 1e-5f);
    __syncthreads();
    float p = 0.f;
    for (int k = tid; k < 384; k += 256) {
        float v = (h1[k] - mean) * rn * clg[d * 384 + k] + clb[d * 384 + k];
        v = gelu_f(v);
        p += v * cw2[d * 384 + k];
    }
    r1[tid] = p;
    __syncthreads();
    for (int o = 128; o > 0; o >>= 1) {
        if (tid < o) r1[tid] += r1[tid + o];
        __syncthreads();
    }
    if (tid == 0) {
        float pred = r1[0] + cb2[d];
        g_gate[b * DD + d] = (cnt > 0.f && pred > 0.f) ? 1.f : 0.f;
    }
}

// ---------------- M[e] = Bu_e^T @ Ad_e^T ----------------
__global__ void m_kernel(const float* __restrict__ bu, const float* __restrict__ ad) {
    int e = blockIdx.x;
    int r = threadIdx.x >> 3, c = threadIdx.x & 7;
    const float* bup = bu + (size_t)e * II * LRK;
    const float* adp = ad + ((size_t)e * LRK + c) * II;
    float s = 0.f;
    for (int i = 0; i < II; i++) s += bup[i * LRK + r] * adp[i];
    g_M[(e * LRK + r) * LRK + c] = s;
}

// ---------------- t = v + SCAL * u @ M ----------------
__global__ void t_kernel() {
    int token = blockIdx.x;
    int er = threadIdx.x;
    int e = er >> 3, r = er & 7;
    __shared__ float su[ELR];
    su[er] = g_u[token * ELR + er];
    __syncthreads();
    float s = 0.f;
#pragma unroll
    for (int q = 0; q < LRK; q++) s += su[e * LRK + q] * g_M[(e * LRK + q) * LRK + r];
    g_t[token * ELR + er] = g_vv[token * ELR + er] + SCALF * s;
}

// ---------------- expert mix ----------------
__global__ void comb_kernel(const float* __restrict__ bd, const float* __restrict__ mask) {
    int token = blockIdx.x;
    int b = token / SS, s = token - b * SS;
    int tid = threadIdx.x;
    __shared__ float r1[256], r2[256];
    __shared__ float sw[16];
    if (tid < EE) {
        float a;
        if (tid == 14) a = 1.f;
        else a = (s > 0 && mask[(s - 1) * DD + tid] > 0.f) ? g_gate[b * DD + tid] : 0.f;
        sw[tid] = a;
    }
    __syncthreads();
    float nact = 0.f;
#pragma unroll
    for (int e = 0; e < EE; e++) nact += sw[e];
    float wt = 1.0f / fmaxf(nact, 1.0f);
    float bo0[3], acc[3] = {0.f, 0.f, 0.f};
#pragma unroll
    for (int i = 0; i < 3; i++) bo0[i] = g_bout[token * HH + tid + i * 256];
    for (int e = 0; e < EE; e++) {
        if (sw[e] == 0.f) continue;
        float t8[8];
        const float* tp = g_t + token * ELR + e * LRK;
#pragma unroll
        for (int r = 0; r < 8; r++) t8[r] = tp[r];
        float o[3];
        float a = 0.f, sq = 0.f;
#pragma unroll
        for (int i = 0; i < 3; i++) {
            int j = tid + i * 256;
            const float* bdp = bd + ((size_t)e * HH + j) * LRK;
            float dv = 0.f;
#pragma unroll
            for (int r = 0; r < 8; r++) dv += t8[r] * bdp[r];
            float ov = bo0[i] + SCALF * dv;
            o[i] = ov; a += ov; sq += ov * ov;
        }
        r1[tid] = a; r2[tid] = sq;
        __syncthreads();
        for (int off = 128; off > 0; off >>= 1) {
            if (tid < off) { r1[tid] += r1[tid + off]; r2[tid] += r2[tid + off]; }
            __syncthreads();
        }
        float mean = r1[0] * (1.0f / 768.0f);
        float var = r2[0] * (1.0f / 768.0f) - mean * mean;
        float rn = rsqrtf(var + 1e-5f);
#pragma unroll
        for (int i = 0; i < 3; i++) acc[i] += wt * (o[i] - mean) * rn;
        __syncthreads();
    }
#pragma unroll
    for (int i = 0; i < 3; i++) {
        int j = tid + i * 256;
        g_h[token * HH + j] = acc[i] + g_res1[token * HH + j];
    }
}

// ---------------- host launcher ----------------
extern "C" void kernel_launch(void* const* d_in, const int* in_sizes, int n_in,
                              void* d_out, int out_size) {
    const float* rf   = (const float*)d_in[0];
    const float* cls  = (const float*)d_in[1];
    const float* ln1g = (const float*)d_in[2];
    const float* ln1b = (const float*)d_in[3];
    const float* ln2g = (const float*)d_in[4];
    const float* ln2b = (const float*)d_in[5];
    const float* wq   = (const float*)d_in[6];
    const float* bq   = (const float*)d_in[7];
    const float* wk   = (const float*)d_in[8];
    const float* bk   = (const float*)d_in[9];
    const float* wv   = (const float*)d_in[10];
    const float* bv   = (const float*)d_in[11];
    const float* wo   = (const float*)d_in[12];
    const float* bo   = (const float*)d_in[13];
    const float* wi   = (const float*)d_in[14];
    const float* bi   = (const float*)d_in[15];
    const float* wof  = (const float*)d_in[16];
    const float* bof  = (const float*)d_in[17];
    const float* lnfg = (const float*)d_in[18];
    const float* lnfb = (const float*)d_in[19];
    const float* au   = (const float*)d_in[20];
    const float* bu   = (const float*)d_in[21];
    const float* ad   = (const float*)d_in[22];
    const float* bd   = (const float*)d_in[23];
    const float* cw1  = (const float*)d_in[24];
    const float* cb1  = (const float*)d_in[25];
    const float* clg  = (const float*)d_in[26];
    const float* clb  = (const float*)d_in[27];
    const float* cw2  = (const float*)d_in[28];
    const float* cb2  = (const float*)d_in[29];
    const float* maskp= (const float*)d_in[30];
    float* out = (float*)d_out;

    float *h, *nx, *q, *k, *v, *ctx, *att, *res1, *nres, *hid, *bout;
    float *u, *vv;
    cudaGetSymbolAddress((void**)&h,    g_h);
    cudaGetSymbolAddress((void**)&nx,   g_nx);
    cudaGetSymbolAddress((void**)&q,    g_q);
    cudaGetSymbolAddress((void**)&k,    g_k);
    cudaGetSymbolAddress((void**)&v,    g_v);
    cudaGetSymbolAddress((void**)&ctx,  g_ctx);
    cudaGetSymbolAddress((void**)&att,  g_att);
    cudaGetSymbolAddress((void**)&res1, g_res1);
    cudaGetSymbolAddress((void**)&nres, g_nres);
    cudaGetSymbolAddress((void**)&hid,  g_hid);
    cudaGetSymbolAddress((void**)&bout, g_bout);
    cudaGetSymbolAddress((void**)&u,    g_u);
    cudaGetSymbolAddress((void**)&vv,   g_vv);

    dim3 t768(HH / 128, TN / 128);      // 6 x 30
    dim3 t3072(II / 128, TN / 128);     // 24 x 30
    dim3 g120((ELR + 63) / 64, TN / 64);
    int nel = TN * HH;
    int nblk = (nel + 255) / 256;

    embed_kernel<<<nblk, 256>>>(rf, cls);

    for (int i = 0; i < LL; i++) {
        ln_kernel<<<TN, 256>>>(h, nullptr, nullptr, nx, ln1g + i * HH, ln1b + i * HH, 1e-12f);
        pgemm_kernel<<<t768, 256>>>(nx, wq + (size_t)i * HH * HH, bq + i * HH, nullptr, q, HH, HH, 0);
        pgemm_kernel<<<t768, 256>>>(nx, wk + (size_t)i * HH * HH, bk + i * HH, nullptr, k, HH, HH, 0);
        pgemm_kernel<<<t768, 256>>>(nx, wv + (size_t)i * HH * HH, bv + i * HH, nullptr, v, HH, HH, 0);
        attn_kernel<<<BQ * NHD, 256>>>();
        pgemm_kernel<<<t768, 256>>>(ctx, wo + (size_t)i * HH * HH, bo + i * HH, nullptr, att, HH, HH, 0);
        // res1 = att + h; nres = LN(res1)
        ln_kernel<<<TN, 256>>>(att, h, res1, nres, ln2g + i * HH, ln2b + i * HH, 1e-12f);
        pgemm_kernel<<<t3072, 256>>>(nres, wi + (size_t)i * II * HH, bi + i * II, nullptr, hid, II, HH, 1);
        if (i & 1) {
            pgemm_kernel<<<t768, 256>>>(hid, wof + (size_t)i * HH * II, bof + i * HH, res1, h, HH, II, 0);
        } else {
            int ei = i / 2;
            pgemm_kernel<<<t768, 256>>>(hid, wof + (size_t)i * HH * II, bof + i * HH, nullptr, bout, HH, II, 0);
            dim3 gc(BQ, DD);
            cls_kernel<<<gc, 256>>>(maskp,
                                    cw1 + (size_t)ei * DD * 384 * HH,
                                    cb1 + (size_t)ei * DD * 384,
                                    clg + (size_t)ei * DD * 384,
                                    clb + (size_t)ei * DD * 384,
                                    cw2 + (size_t)ei * DD * 384,
                                    cb2 + (size_t)ei * DD);
            m_kernel<<<EE, 64>>>(bu + (size_t)ei * EE * II * LRK,
                                 ad + (size_t)ei * EE * LRK * II);
            gemm_kernel<<<g120, 256>>>(nres, au + (size_t)ei * EE * LRK * HH, nullptr, nullptr, u, ELR, HH, 0);
            gemm_kernel<<<g120, 256>>>(hid, ad + (size_t)ei * EE * LRK * II, nullptr, nullptr, vv, ELR, II, 0);
            t_kernel<<<TN, ELR>>>();
            comb_kernel<<<TN, 256>>>(bd + (size_t)ei * EE * HH * LRK, maskp);
        }
    }
    ln_kernel<<<TN, 256>>>(h, nullptr, nullptr, out, lnfg, lnfb, 1e-12f);
}